// round 11
// baseline (speedup 1.0000x reference)
#include <cuda_runtime.h>
#include <math.h>

// ---------------------------------------------------------------------------
// PhysicalLayer forward, sm_103a.  (Round-11: K-split the proven R6 apply)
//   FO = M f M^T, M = F*T built by O(N^2) sliding-window recurrence.
//   Apply GEMMs: R6 inner loop verbatim (2k x 4r, double-buffered,
//   warp-uniform x) but K-split 4 ways -> grid (8,16,4)=512 blocks,
//   25.6KBx2 smem, 3 blocks/SM, atomic partial accumulation.
// ---------------------------------------------------------------------------

#define GN  500
#define MTS 512
#define SEG 63

// apply tiling
#define TK  64
#define TR  32
#define KK  25
#define NSPLIT 4
#define NPERZ 125
#define NCH 5
#define WB  (KK * TK * 8)     // 12800 B: w float2 [KK][64]
#define XB  (KK * TR * 16)    // 12800 B: x float4 [KK][32]
#define BUFB (WB + XB)        // 25600 B

typedef unsigned long long u64;

__device__ float2 g_field[GN * GN];
__device__ float2 g_A[GN * GN];
__device__ float2 g_B[GN * GN];
__device__ float2 g_MT[GN * MTS];   // MT[m*512 + k] = M[k,m]; cols 500.. stay 0
__device__ float  g_tg[GN * GN];
__device__ float2 g_p[1024];
__device__ float2 g_W500f[GN];
__device__ float2 g_W500i[GN];
__device__ float  g_intens[128];
__device__ float  g_canvas[2 * 200 * 200];

// ---------------- f32x2 packed helpers -------------------------------------
__device__ __forceinline__ u64 ffma2(u64 a, u64 b, u64 c) {
    u64 d;
    asm("fma.rn.f32x2 %0, %1, %2, %3;" : "=l"(d) : "l"(a), "l"(b), "l"(c));
    return d;
}
__device__ __forceinline__ u64 pk2(float lo, float hi) {
    u64 r;
    asm("mov.b64 %0, {%1, %2};" : "=l"(r) : "f"(lo), "f"(hi));
    return r;
}
__device__ __forceinline__ float2 unpk(u64 v) {
    float lo, hi;
    asm("mov.b64 {%0, %1}, %2;" : "=f"(lo), "=f"(hi) : "l"(v));
    return make_float2(lo, hi);
}

// ---------------- fused prep: tables + zero + field + tg -------------------
__global__ void k_prep(const float* __restrict__ mp,
                       const float* __restrict__ mr,
                       const float2* __restrict__ B1,
                       const float* __restrict__ gam, float sK) {
    int i = blockIdx.x * blockDim.x + threadIdx.x;
    const double PI = 3.14159265358979323846;
    if (i < 1024) {
        float2 v = make_float2(0.f, 0.f);
        if (i < 1000) {
            double alpha = PI * 1.33 / (5.61e-7 * 0.006);
            double x = (double)(i - 499) * 1e-6;
            double th = alpha * x * x;
            double s, c;
            sincos(th, &s, &c);
            v = make_float2((float)c, (float)s);
        }
        g_p[i] = v;
    }
    if (i < GN) {
        double ang = -2.0 * PI * (double)i / (double)GN;
        double s, c;
        sincos(ang, &s, &c);
        g_W500f[i] = make_float2((float)c, (float)s);
        g_W500i[i] = make_float2((float)c, (float)(-s));
    }
    if (i < 2 * 200 * 200) g_canvas[i] = 0.f;
    if (i < 128) g_intens[i] = 0.f;
    if (i < GN * GN) {
        // zero atomic-accumulation targets
        g_A[i] = make_float2(0.f, 0.f);
        g_B[i] = make_float2(0.f, 0.f);
        float s, c;
        sincosf(mp[i], &s, &c);
        float m = mr[i];
        float2 b = B1[i];
        float er = m * c, ei = m * s;
        g_field[i] = make_float2(b.x * er - b.y * ei, b.x * ei + b.y * er);
        int u = i / GN, v2 = i % GN;
        int su = (u + 250) % GN, sv = (v2 + 250) % GN;
        g_tg[i] = sK * gam[su * GN + sv];
    }
}

// ---------------- M build via sliding-window recurrence --------------------
__global__ __launch_bounds__(128) void k_buildM() {
    __shared__ float2 sWf[GN];
    __shared__ float2 sp[1000];
    for (int i = threadIdx.x; i < 1000; i += 128) {
        if (i < GN) sWf[i] = g_W500f[i];
        sp[i] = g_p[i];
    }
    __syncthreads();

    int t = blockIdx.x * blockDim.x + threadIdx.x;
    if (t >= GN * 8) return;
    int k = t >> 3, seg = t & 7;
    int m0 = seg * SEG;
    int mend = m0 + SEG; if (mend > GN) mend = GN;

    int idx0 = (k * m0) % GN;
    int idx = (GN - idx0) % GN;
    float gx = 0.f, gy = 0.f;
    for (int s = 0; s < GN; s++) {
        float2 w = sWf[idx];
        float2 pv = sp[500 - m0 + s];
        gx = fmaf(w.x, pv.x, gx); gx = fmaf(-w.y, pv.y, gx);
        gy = fmaf(w.x, pv.y, gy); gy = fmaf(w.y, pv.x, gy);
        idx += k; if (idx >= GN) idx -= GN;
    }

    int idx3 = idx0;
    int idx1 = idx0 + k; if (idx1 >= GN) idx1 -= GN;
    int idx2 = (k * (499 - m0)) % GN;
    for (int m = m0; m < mend; m++) {
        float2 w3 = sWf[idx3];
        float Mx = (w3.x * gx - w3.y * gy) * 1e-3f;
        float My = (w3.x * gy + w3.y * gx) * 1e-3f;
        g_MT[m * MTS + k] = make_float2(Mx, My);
        float2 w1 = sWf[idx1];
        float2 pa = sp[499 - m];
        gx = fmaf(w1.x, pa.x, gx); gx = fmaf(w1.y, pa.y, gx);
        gy = fmaf(w1.x, pa.y, gy); gy = fmaf(-w1.y, pa.x, gy);
        float2 w2 = sWf[idx2];
        float2 pb = sp[999 - m];
        gx = fmaf(-w2.x, pb.x, gx); gx = fmaf(w2.y, pb.y, gx);
        gy = fmaf(-w2.x, pb.y, gy); gy = fmaf(-w2.y, pb.x, gy);
        idx3 += k; if (idx3 >= GN) idx3 -= GN;
        idx1 += k; if (idx1 >= GN) idx1 -= GN;
        idx2 -= k; if (idx2 < 0) idx2 += GN;
    }
}

// ---------------- apply pass (R6 loop, K-split 4, atomic accumulate) -------
// 256 threads: tkg=tid&31 (2 k's each), trg=tid>>5 = warp id (4 r's each).
// x is warp-uniform -> broadcast LDS. Double-buffered smem.
__global__ __launch_bounds__(256, 3) void k_apply(const float2* __restrict__ in,
                                                  float2* __restrict__ out) {
    extern __shared__ char sh[];
    int k0 = blockIdx.x * TK;
    int r0 = blockIdx.y * TR;
    int nz = blockIdx.z * NPERZ;
    int tid = threadIdx.x;
    int tkg = tid & 31;
    int trg = tid >> 5;

    u64 acc[2][4] = {};

    // stage chunk 0
    {
        float4* swb = (float4*)(sh);
        float4* sxb = (float4*)(sh + WB);
#pragma unroll
        for (int j = 0; j < 4; j++) {
            int i = tid + j * 256;
            if (i < 800) {
                int nn = i >> 5, kk2 = i & 31;
                swb[nn * 32 + kk2] =
                    *(const float4*)&g_MT[(size_t)(nz + nn) * MTS + k0 + 2 * kk2];
            }
        }
#pragma unroll
        for (int j = 0; j < 4; j++) {
            int i = tid + j * 256;
            if (i < 800) {
                int rr = i & 31, nn = i >> 5;
                int r = r0 + rr;
                float2 v = make_float2(0.f, 0.f);
                if (r < GN) v = in[(size_t)r * GN + nz + nn];
                sxb[nn * 32 + rr] = make_float4(v.x, v.y, -v.y, v.x);
            }
        }
    }
    __syncthreads();

    for (int c = 0; c < NCH; c++) {
        // prefetch chunk c+1 into registers
        float4 pw[4];
        float2 px[4];
        if (c + 1 < NCH) {
            int n0p = nz + (c + 1) * KK;
#pragma unroll
            for (int j = 0; j < 4; j++) {
                int i = tid + j * 256;
                if (i < 800) {
                    int nn = i >> 5, kk2 = i & 31;
                    pw[j] = *(const float4*)&g_MT[(size_t)(n0p + nn) * MTS +
                                                  k0 + 2 * kk2];
                }
            }
#pragma unroll
            for (int j = 0; j < 4; j++) {
                int i = tid + j * 256;
                if (i < 800) {
                    int rr = i & 31, nn = i >> 5;
                    int r = r0 + rr;
                    float2 v = make_float2(0.f, 0.f);
                    if (r < GN) v = in[(size_t)r * GN + n0p + nn];
                    px[j] = v;
                }
            }
        }

        // compute on buffer c&1
        {
            const char* base = sh + (c & 1) * BUFB;
            const float4* swc = (const float4*)base;                 // [KK][32]
            const ulonglong2* sxc = (const ulonglong2*)(base + WB);  // [KK][32]
#pragma unroll 5
            for (int nn = 0; nn < KK; nn++) {
                float4 wv = swc[nn * 32 + tkg];
                u64 wR0 = pk2(wv.x, wv.x), wI0 = pk2(wv.y, wv.y);
                u64 wR1 = pk2(wv.z, wv.z), wI1 = pk2(wv.w, wv.w);
                ulonglong2 x0 = sxc[nn * 32 + 4 * trg + 0];
                ulonglong2 x1 = sxc[nn * 32 + 4 * trg + 1];
                ulonglong2 x2 = sxc[nn * 32 + 4 * trg + 2];
                ulonglong2 x3 = sxc[nn * 32 + 4 * trg + 3];

                acc[0][0] = ffma2(wR0, x0.x, acc[0][0]);
                acc[0][0] = ffma2(wI0, x0.y, acc[0][0]);
                acc[0][1] = ffma2(wR0, x1.x, acc[0][1]);
                acc[0][1] = ffma2(wI0, x1.y, acc[0][1]);
                acc[0][2] = ffma2(wR0, x2.x, acc[0][2]);
                acc[0][2] = ffma2(wI0, x2.y, acc[0][2]);
                acc[0][3] = ffma2(wR0, x3.x, acc[0][3]);
                acc[0][3] = ffma2(wI0, x3.y, acc[0][3]);
                acc[1][0] = ffma2(wR1, x0.x, acc[1][0]);
                acc[1][0] = ffma2(wI1, x0.y, acc[1][0]);
                acc[1][1] = ffma2(wR1, x1.x, acc[1][1]);
                acc[1][1] = ffma2(wI1, x1.y, acc[1][1]);
                acc[1][2] = ffma2(wR1, x2.x, acc[1][2]);
                acc[1][2] = ffma2(wI1, x2.y, acc[1][2]);
                acc[1][3] = ffma2(wR1, x3.x, acc[1][3]);
                acc[1][3] = ffma2(wI1, x3.y, acc[1][3]);
            }
        }

        // store prefetched chunk into the other buffer
        if (c + 1 < NCH) {
            char* base = sh + ((c + 1) & 1) * BUFB;
            float4* swb4 = (float4*)base;
            float4* sxb = (float4*)(base + WB);
#pragma unroll
            for (int j = 0; j < 4; j++) {
                int i = tid + j * 256;
                if (i < 800) {
                    int nn = i >> 5, kk2 = i & 31;
                    swb4[nn * 32 + kk2] = pw[j];
                }
            }
#pragma unroll
            for (int j = 0; j < 4; j++) {
                int i = tid + j * 256;
                if (i < 800) {
                    int rr = i & 31, nn = i >> 5;
                    float2 v = px[j];
                    sxb[nn * 32 + rr] = make_float4(v.x, v.y, -v.y, v.x);
                }
            }
        }
        __syncthreads();
    }

    // atomic accumulate partials: k = k0 + 2*tkg + q, r = r0 + 4*trg + s
    float* fo = (float*)out;
    int rb = r0 + 4 * trg;
#pragma unroll
    for (int q = 0; q < 2; q++) {
        int k = k0 + 2 * tkg + q;
        if (k >= GN) continue;
#pragma unroll
        for (int s = 0; s < 4; s++) {
            int r = rb + s;
            if (r >= GN) continue;
            float2 v = unpk(acc[q][s]);
            atomicAdd(&fo[((size_t)k * GN + r) * 2 + 0], v.x);
            atomicAdd(&fo[((size_t)k * GN + r) * 2 + 1], v.y);
        }
    }
}

// ---------------- per-emitter intensity: warp-owned emitter ranges ---------
__global__ __launch_bounds__(128) void k_emit(const int* __restrict__ xyz) {
    __shared__ float2 sfo[GN];
    __shared__ float  stg[GN];
    __shared__ float2 sW[GN];
    int u = blockIdx.x;

    const float2* fo = g_B + (size_t)u * GN;   // FO lives in g_B
    const float*  tg = g_tg + (size_t)u * GN;
    for (int i = threadIdx.x; i < GN; i += 128) {
        sfo[i] = fo[i];
        stg[i] = tg[i];
        sW[i]  = g_W500i[i];
    }
    __syncthreads();

    int lane = threadIdx.x & 31;
    int wid = threadIdx.x >> 5;

    for (int e = wid * 32; e < wid * 32 + 32; e++) {
        int x0 = xyz[e * 3 + 0];
        int z = xyz[e * 3 + 2];
        float xf = (float)(x0 - 100);
        int c = 249 + z;
        int idx = (c * lane) % GN;
        int step = (c * 32) % GN;

        float sx = 0.f, sy = 0.f;
        for (int v = lane; v < GN; v += 32) {
            float arg = stg[v] * xf;  // f32 rounding matches reference
            float nq = rintf(arg * 0.15915494309189535f);
            float rr = fmaf(nq, -6.28125f, arg);
            rr = fmaf(nq, -1.9353072e-3f, rr);
            float sn, cs;
            __sincosf(rr, &sn, &cs);
            float2 f = sfo[v];
            float pr = f.x * cs - f.y * sn;
            float pi = f.x * sn + f.y * cs;
            float2 w = sW[idx];
            sx = fmaf(pr, w.x, sx); sx = fmaf(-pi, w.y, sx);
            sy = fmaf(pr, w.y, sy); sy = fmaf(pi, w.x, sy);
            idx += step; if (idx >= GN) idx -= GN;
        }
#pragma unroll
        for (int o = 16; o > 0; o >>= 1) {
            sx += __shfl_down_sync(0xffffffffu, sx, o);
            sy += __shfl_down_sync(0xffffffffu, sy, o);
        }
        if (lane == 0)
            atomicAdd(&g_intens[e], (sx * sx + sy * sy) * 8e-9f);  // 1/500^3
    }
}

// ---------------- scatter psf patches into canvas --------------------------
__global__ void k_scatter(const int* __restrict__ xyz,
                          const float* __restrict__ psf) {
    int tid = blockIdx.x * blockDim.x + threadIdx.x;
    if (tid >= 128 * 961) return;
    int e = tid / 961, p = tid % 961;
    int b = e >> 6;
    int x0 = xyz[e * 3 + 0];
    int y0 = xyz[e * 3 + 1];
    int z = xyz[e * 3 + 2];
    int r = p / 31, cc = p % 31;
    float val = psf[z * 961 + p] * g_intens[e];
    int row = x0 + r - 15;
    int col = y0 + cc - 15;
    atomicAdd(&g_canvas[b * 40000 + row * 200 + col], val);
}

// ---------------- noise model + output -------------------------------------
__global__ void k_final(const float* __restrict__ ng,
                        const float* __restrict__ np_,
                        float* __restrict__ out) {
    int i = blockIdx.x * blockDim.x + threadIdx.x;
    if (i >= 2 * 200 * 200) return;
    float a = g_canvas[i] / 50000.0f + 100.0f;  // imgs3D + UNIF_BG
    float b = a + 100000.0f;
    float t = fmaf(2.0e8f, ng[i], 3.0e8f);
    float inp = b + t;
    if (inp <= 0.0f) inp = 0.0f;
    float noisy = inp + 100.0f * sqrtf(inp) * np_[i];
    if (noisy <= 10.0f) noisy = 1.0f;
    noisy = fminf(noisy, 4.0e9f);
    out[i] = noisy / 4.0e9f;
}

// ---------------------------------------------------------------------------
extern "C" void kernel_launch(void* const* d_in, const int* in_sizes, int n_in,
                              void* d_out, int out_size) {
    const float*  mask_param = (const float*)d_in[0];
    const int*    xyz        = (const int*)d_in[1];
    // d_in[2] = nphotons (unused by reference)
    const float2* B1         = (const float2*)d_in[3];
    // d_in[4] = Q1 (replaced by separable p-vector)
    const float*  mask_real  = (const float*)d_in[5];
    const float*  gamma_c    = (const float*)d_in[6];
    const float*  psf        = (const float*)d_in[7];
    const float*  ngauss     = (const float*)d_in[8];
    const float*  npoiss     = (const float*)d_in[9];
    float*        out        = (float*)d_out;

    double Kd = 2.0 * 1.33 * 3.14159265358979323846 / 5.61e-7;
    float sK = (float)(Kd * 1e-6);

    float2 *fld, *bA, *bB;
    cudaGetSymbolAddress((void**)&fld, g_field);
    cudaGetSymbolAddress((void**)&bA, g_A);
    cudaGetSymbolAddress((void**)&bB, g_B);

    const int BT = 256;
    const int SMEM_APPLY = 2 * BUFB;  // 51.2KB
    cudaFuncSetAttribute(k_apply, cudaFuncAttributeMaxDynamicSharedMemorySize,
                         SMEM_APPLY);

    // fused setup (zeroes atomic accumulation targets g_A, g_B)
    k_prep<<<(GN * GN + BT - 1) / BT, BT>>>(mask_param, mask_real, B1,
                                            gamma_c, sK);

    // M = 1e-3 * F * T via sliding-window recurrence (transposed into g_MT)
    k_buildM<<<(GN * 8 + 127) / 128, 128>>>();

    // FO = M f M^T  (two transposing apply-passes, K-split 4) -> g_B
    dim3 pg((GN + TK - 1) / TK, (GN + TR - 1) / TR, NSPLIT);  // 8x16x4 = 512
    k_apply<<<pg, 256, SMEM_APPLY>>>(fld, bA);
    k_apply<<<pg, 256, SMEM_APPLY>>>(bA, bB);

    // per-emitter intensities (4 warps x 32 emitters per block)
    k_emit<<<GN, 128>>>(xyz);

    // patches -> canvas
    k_scatter<<<(128 * 961 + BT - 1) / BT, BT>>>(xyz, psf);

    // noise model -> output
    k_final<<<(2 * 200 * 200 + BT - 1) / BT, BT>>>(ngauss, npoiss, out);
}

// round 12
// speedup vs baseline: 1.2831x; 1.2831x over previous
#include <cuda_runtime.h>
#include <math.h>

// ---------------------------------------------------------------------------
// PhysicalLayer forward, sm_103a.  (Round-12: FFT-based transform chain)
//   Propagation out = 1e-6 * (T f T^T) as two separable length-1024 circular
//   convolutions (alias-free for the cropped outputs). FO = fft2(out) via
//   Bluestein chirp-z, also as 1024-point convolutions. One batched radix-2
//   Stockham FFT kernel does all 4 passes. Emit/scatter/final unchanged.
// ---------------------------------------------------------------------------

#define GN 500

typedef unsigned long long u64;

__device__ float2 g_field[GN * GN];
__device__ float2 g_A[GN * GN];
__device__ float2 g_B[GN * GN];
__device__ float  g_tg[GN * GN];
__device__ float2 g_p[1024];       // q kernel: p[0..999], zeros beyond
__device__ float2 g_c[1024];       // bluestein kernel c
__device__ float2 g_chirp[GN];     // w_n = e^{-i pi n^2/500}
__device__ float2 g_W1024[1024];   // e^{-2 pi i t/1024}
__device__ float2 g_Kp[1024];      // FFT1024(q) * 1e-3/1024
__device__ float2 g_Kb[1024];      // FFT1024(c) * 1/1024
__device__ float2 g_W500i[GN];
__device__ float  g_intens[128];
__device__ float  g_canvas[2 * 200 * 200];

__device__ __forceinline__ float2 cadd(float2 a, float2 b) {
    return make_float2(a.x + b.x, a.y + b.y);
}
__device__ __forceinline__ float2 csub(float2 a, float2 b) {
    return make_float2(a.x - b.x, a.y - b.y);
}
__device__ __forceinline__ float2 cmul(float2 a, float2 b) {
    return make_float2(a.x * b.x - a.y * b.y, a.x * b.y + a.y * b.x);
}
__device__ __forceinline__ float2 cmulc(float2 a, float2 b) {  // a * conj(b)
    return make_float2(a.x * b.x + a.y * b.y, a.y * b.x - a.x * b.y);
}

// ---------------- fused prep: tables + zero + field + tg -------------------
__global__ void k_prep(const float* __restrict__ mp,
                       const float* __restrict__ mr,
                       const float2* __restrict__ B1,
                       const float* __restrict__ gam, float sK) {
    int i = blockIdx.x * blockDim.x + threadIdx.x;
    const double PI = 3.14159265358979323846;
    if (i < 1024) {
        // q kernel (propagation chirp), zero-padded
        float2 v = make_float2(0.f, 0.f);
        if (i < 1000) {
            double alpha = PI * 1.33 / (5.61e-7 * 0.006);
            double x = (double)(i - 499) * 1e-6;
            double th = alpha * x * x;
            double s, c;
            sincos(th, &s, &c);
            v = make_float2((float)c, (float)s);
        }
        g_p[i] = v;
        // forward 1024 twiddles
        {
            double ang = -2.0 * PI * (double)i / 1024.0;
            double s, c;
            sincos(ang, &s, &c);
            g_W1024[i] = make_float2((float)c, (float)s);
        }
        // bluestein kernel c: b_n = e^{+i pi n^2/500}, even, with zero gap
        {
            float2 cv = make_float2(0.f, 0.f);
            long n = -1;
            if (i < 500) n = i;
            else if (i >= 525) n = 1024 - i;
            if (n >= 0) {
                double th = PI * (double)(n * n) / 500.0;
                double s, c;
                sincos(th, &s, &c);
                cv = make_float2((float)c, (float)s);
            }
            g_c[i] = cv;
        }
    }
    if (i < GN) {
        double th = PI * (double)((long)i * i) / 500.0;
        double s, c;
        sincos(th, &s, &c);
        g_chirp[i] = make_float2((float)c, (float)(-s));   // e^{-i th}
        double ang = -2.0 * PI * (double)i / (double)GN;
        double s2, c2;
        sincos(ang, &s2, &c2);
        g_W500i[i] = make_float2((float)c2, (float)(-s2)); // conj fwd = inv
    }
    if (i < 2 * 200 * 200) g_canvas[i] = 0.f;
    if (i < 128) g_intens[i] = 0.f;
    if (i < GN * GN) {
        float s, c;
        sincosf(mp[i], &s, &c);
        float m = mr[i];
        float2 b = B1[i];
        float er = m * c, ei = m * s;
        g_field[i] = make_float2(b.x * er - b.y * ei, b.x * ei + b.y * er);
        int u = i / GN, v2 = i % GN;
        int su = (u + 250) % GN, sv = (v2 + 250) % GN;
        g_tg[i] = sK * gam[su * GN + sv];
    }
}

// ---------------- direct 1024-DFT for the two kernel tables ----------------
// grid (1024, 2), 128 threads. y=0: Kp from g_p; y=1: Kb from g_c.
__global__ __launch_bounds__(128) void k_tabdft() {
    __shared__ float rx[4], ry[4];
    int k = blockIdx.x;
    int which = blockIdx.y;
    const float2* src = which ? g_c : g_p;
    int t = threadIdx.x;
    int idx = (k * t) & 1023;
    int step = (k * 128) & 1023;
    float ax = 0.f, ay = 0.f;
    for (; t < 1024; t += 128) {
        float2 s = src[t];
        float2 w = g_W1024[idx];
        ax = fmaf(s.x, w.x, ax); ax = fmaf(-s.y, w.y, ax);
        ay = fmaf(s.x, w.y, ay); ay = fmaf(s.y, w.x, ay);
        idx = (idx + step) & 1023;
    }
    int lane = threadIdx.x & 31, wid = threadIdx.x >> 5;
#pragma unroll
    for (int o = 16; o > 0; o >>= 1) {
        ax += __shfl_down_sync(0xffffffffu, ax, o);
        ay += __shfl_down_sync(0xffffffffu, ay, o);
    }
    if (lane == 0) { rx[wid] = ax; ry[wid] = ay; }
    __syncthreads();
    if (threadIdx.x == 0) {
        float Sx = rx[0] + rx[1] + rx[2] + rx[3];
        float Sy = ry[0] + ry[1] + ry[2] + ry[3];
        float sc = which ? (1.0f / 1024.0f) : (1e-3f / 1024.0f);
        if (which) g_Kb[k] = make_float2(Sx * sc, Sy * sc);
        else       g_Kp[k] = make_float2(Sx * sc, Sy * sc);
    }
}

// ---------------- batched FFT-conv pass ------------------------------------
// 2 rows per block (grid 250), 256 threads. mode 0: propagation conv
// (pad -> FFT -> xKp -> IFFT -> take [500..999]); mode 1: bluestein DFT
// (x*chirp pad -> FFT -> xKb -> IFFT -> x chirp, take [0..499]).
// Output written transposed; applying the pass twice = 2D transform, natural.
__global__ __launch_bounds__(256) void k_fconv(const float2* __restrict__ in,
                                               float2* __restrict__ out,
                                               int mode) {
    extern __shared__ float2 sm[];
    float2* buf0 = sm;          // [2][1024]
    float2* buf1 = sm + 2048;   // [2][1024]
    float2* sW   = sm + 4096;   // [1024]
    int r0 = blockIdx.x * 2;
    int tid = threadIdx.x;

    for (int i = tid; i < 1024; i += 256) sW[i] = g_W1024[i];

    // load rows r0, r0+1; chirp-multiply for bluestein; zero-pad to 1024
    for (int i = tid; i < 2048; i += 256) {
        int b = i >> 10, t = i & 1023;
        float2 v = make_float2(0.f, 0.f);
        if (t < 500) {
            v = in[(size_t)(r0 + b) * GN + t];
            if (mode) v = cmul(v, g_chirp[t]);
        }
        buf0[i] = v;
    }
    __syncthreads();

    // forward FFT: 10 radix-2 Stockham stages (natural order in/out)
    float2 *cur = buf0, *nxt = buf1;
    int m = 1;
#pragma unroll 1
    for (int st = 0; st < 10; st++) {
        for (int i = tid; i < 1024; i += 256) {
            int b = i >> 9, bf = i & 511;
            int base = b << 10;
            float2 c0 = cur[base + bf];
            float2 c1 = cur[base + bf + 512];
            int jm = bf & ~(m - 1);
            float2 w = sW[jm];
            int o = base + bf + jm;
            nxt[o] = cadd(c0, c1);
            nxt[o + m] = cmul(csub(c0, c1), w);
        }
        float2* tsw = cur; cur = nxt; nxt = tsw;
        m <<= 1;
        __syncthreads();
    }
    // result in cur (== buf0)

    // pointwise kernel multiply
    const float2* K = mode ? g_Kb : g_Kp;
    for (int i = tid; i < 2048; i += 256)
        cur[i] = cmul(cur[i], K[i & 1023]);
    __syncthreads();

    // inverse FFT (conjugate twiddles; normalization folded into K)
    m = 1;
#pragma unroll 1
    for (int st = 0; st < 10; st++) {
        for (int i = tid; i < 1024; i += 256) {
            int b = i >> 9, bf = i & 511;
            int base = b << 10;
            float2 c0 = cur[base + bf];
            float2 c1 = cur[base + bf + 512];
            int jm = bf & ~(m - 1);
            float2 w = sW[jm];
            int o = base + bf + jm;
            nxt[o] = cadd(c0, c1);
            nxt[o + m] = cmulc(csub(c0, c1), w);
        }
        float2* tsw = cur; cur = nxt; nxt = tsw;
        m <<= 1;
        __syncthreads();
    }

    // extract + transposed write (pairs of rows -> 16B contiguous)
    if (mode == 0) {
        for (int i = tid; i < 1000; i += 256) {
            int j = i >> 1, b = i & 1;
            out[(size_t)j * GN + r0 + b] = cur[(b << 10) + 500 + j];
        }
    } else {
        for (int i = tid; i < 1000; i += 256) {
            int k = i >> 1, b = i & 1;
            out[(size_t)k * GN + r0 + b] =
                cmul(cur[(b << 10) + k], g_chirp[k]);
        }
    }
}

// ---------------- per-emitter intensity: warp-owned emitter ranges ---------
__global__ __launch_bounds__(128) void k_emit(const int* __restrict__ xyz) {
    __shared__ float2 sfo[GN];
    __shared__ float  stg[GN];
    __shared__ float2 sW[GN];
    int u = blockIdx.x;

    const float2* fo = g_B + (size_t)u * GN;   // FO lives in g_B
    const float*  tg = g_tg + (size_t)u * GN;
    for (int i = threadIdx.x; i < GN; i += 128) {
        sfo[i] = fo[i];
        stg[i] = tg[i];
        sW[i]  = g_W500i[i];
    }
    __syncthreads();

    int lane = threadIdx.x & 31;
    int wid = threadIdx.x >> 5;

    for (int e = wid * 32; e < wid * 32 + 32; e++) {
        int x0 = xyz[e * 3 + 0];
        int z = xyz[e * 3 + 2];
        float xf = (float)(x0 - 100);
        int c = 249 + z;
        int idx = (c * lane) % GN;
        int step = (c * 32) % GN;

        float sx = 0.f, sy = 0.f;
        for (int v = lane; v < GN; v += 32) {
            float arg = stg[v] * xf;  // f32 rounding matches reference
            float nq = rintf(arg * 0.15915494309189535f);
            float rr = fmaf(nq, -6.28125f, arg);
            rr = fmaf(nq, -1.9353072e-3f, rr);
            float sn, cs;
            __sincosf(rr, &sn, &cs);
            float2 f = sfo[v];
            float pr = f.x * cs - f.y * sn;
            float pi = f.x * sn + f.y * cs;
            float2 w = sW[idx];
            sx = fmaf(pr, w.x, sx); sx = fmaf(-pi, w.y, sx);
            sy = fmaf(pr, w.y, sy); sy = fmaf(pi, w.x, sy);
            idx += step; if (idx >= GN) idx -= GN;
        }
#pragma unroll
        for (int o = 16; o > 0; o >>= 1) {
            sx += __shfl_down_sync(0xffffffffu, sx, o);
            sy += __shfl_down_sync(0xffffffffu, sy, o);
        }
        if (lane == 0)
            atomicAdd(&g_intens[e], (sx * sx + sy * sy) * 8e-9f);  // 1/500^3
    }
}

// ---------------- scatter psf patches into canvas --------------------------
__global__ void k_scatter(const int* __restrict__ xyz,
                          const float* __restrict__ psf) {
    int tid = blockIdx.x * blockDim.x + threadIdx.x;
    if (tid >= 128 * 961) return;
    int e = tid / 961, p = tid % 961;
    int b = e >> 6;
    int x0 = xyz[e * 3 + 0];
    int y0 = xyz[e * 3 + 1];
    int z = xyz[e * 3 + 2];
    int r = p / 31, cc = p % 31;
    float val = psf[z * 961 + p] * g_intens[e];
    int row = x0 + r - 15;
    int col = y0 + cc - 15;
    atomicAdd(&g_canvas[b * 40000 + row * 200 + col], val);
}

// ---------------- noise model + output -------------------------------------
__global__ void k_final(const float* __restrict__ ng,
                        const float* __restrict__ np_,
                        float* __restrict__ out) {
    int i = blockIdx.x * blockDim.x + threadIdx.x;
    if (i >= 2 * 200 * 200) return;
    float a = g_canvas[i] / 50000.0f + 100.0f;  // imgs3D + UNIF_BG
    float b = a + 100000.0f;
    float t = fmaf(2.0e8f, ng[i], 3.0e8f);
    float inp = b + t;
    if (inp <= 0.0f) inp = 0.0f;
    float noisy = inp + 100.0f * sqrtf(inp) * np_[i];
    if (noisy <= 10.0f) noisy = 1.0f;
    noisy = fminf(noisy, 4.0e9f);
    out[i] = noisy / 4.0e9f;
}

// ---------------------------------------------------------------------------
extern "C" void kernel_launch(void* const* d_in, const int* in_sizes, int n_in,
                              void* d_out, int out_size) {
    const float*  mask_param = (const float*)d_in[0];
    const int*    xyz        = (const int*)d_in[1];
    // d_in[2] = nphotons (unused by reference)
    const float2* B1         = (const float2*)d_in[3];
    // d_in[4] = Q1 (replaced by separable p-vector)
    const float*  mask_real  = (const float*)d_in[5];
    const float*  gamma_c    = (const float*)d_in[6];
    const float*  psf        = (const float*)d_in[7];
    const float*  ngauss     = (const float*)d_in[8];
    const float*  npoiss     = (const float*)d_in[9];
    float*        out        = (float*)d_out;

    double Kd = 2.0 * 1.33 * 3.14159265358979323846 / 5.61e-7;
    float sK = (float)(Kd * 1e-6);

    float2 *fld, *bA, *bB;
    cudaGetSymbolAddress((void**)&fld, g_field);
    cudaGetSymbolAddress((void**)&bA, g_A);
    cudaGetSymbolAddress((void**)&bB, g_B);

    const int BT = 256;
    const int SMEM_FFT = 5120 * (int)sizeof(float2);  // 40KB

    // fused setup
    k_prep<<<(GN * GN + BT - 1) / BT, BT>>>(mask_param, mask_real, B1,
                                            gamma_c, sK);

    // kernel-spectrum tables Kp, Kb
    k_tabdft<<<dim3(1024, 2), 128>>>();

    // out = 1e-6 T f T^T (two conv passes), FO = F out F^T (two bluestein)
    k_fconv<<<250, 256, SMEM_FFT>>>(fld, bA, 0);
    k_fconv<<<250, 256, SMEM_FFT>>>(bA, bB, 0);
    k_fconv<<<250, 256, SMEM_FFT>>>(bB, bA, 1);
    k_fconv<<<250, 256, SMEM_FFT>>>(bA, bB, 1);   // FO -> g_B

    // per-emitter intensities (4 warps x 32 emitters per block)
    k_emit<<<GN, 128>>>(xyz);

    // patches -> canvas
    k_scatter<<<(128 * 961 + BT - 1) / BT, BT>>>(xyz, psf);

    // noise model -> output
    k_final<<<(2 * 200 * 200 + BT - 1) / BT, BT>>>(ngauss, npoiss, out);
}

// round 13
// speedup vs baseline: 1.3850x; 1.0794x over previous
#include <cuda_runtime.h>
#include <math.h>

// ---------------------------------------------------------------------------
// PhysicalLayer forward, sm_103a.  (Round-13: radix-4 FFT stages)
//   Propagation as separable 1024-pt circular convolutions (alias-free for
//   the cropped outputs); FO = fft2 via Bluestein. Radix-4 Stockham stages
//   (register-fused pairs of the proven radix-2 stages — identical FP ops).
// ---------------------------------------------------------------------------

#define GN 500

typedef unsigned long long u64;

__device__ float2 g_field[GN * GN];
__device__ float2 g_A[GN * GN];
__device__ float2 g_B[GN * GN];
__device__ float  g_tg[GN * GN];
__device__ float2 g_p[1024];       // q kernel: p[0..999], zeros beyond
__device__ float2 g_c[1024];       // bluestein kernel c
__device__ float2 g_chirp[GN];     // w_n = e^{-i pi n^2/500}
__device__ float2 g_W1024[1024];   // e^{-2 pi i t/1024}
__device__ float2 g_Kp[1024];      // FFT1024(q) * 1e-3/1024
__device__ float2 g_Kb[1024];      // FFT1024(c) * 1/1024
__device__ float2 g_W500i[GN];
__device__ float  g_intens[128];
__device__ float  g_canvas[2 * 200 * 200];

__device__ __forceinline__ float2 cadd(float2 a, float2 b) {
    return make_float2(a.x + b.x, a.y + b.y);
}
__device__ __forceinline__ float2 csub(float2 a, float2 b) {
    return make_float2(a.x - b.x, a.y - b.y);
}
__device__ __forceinline__ float2 cmul(float2 a, float2 b) {
    return make_float2(a.x * b.x - a.y * b.y, a.x * b.y + a.y * b.x);
}
__device__ __forceinline__ float2 cmulc(float2 a, float2 b) {  // a * conj(b)
    return make_float2(a.x * b.x + a.y * b.y, a.y * b.x - a.x * b.y);
}

// ---------------- fused prep: tables + zero + field + tg -------------------
__global__ void k_prep(const float* __restrict__ mp,
                       const float* __restrict__ mr,
                       const float2* __restrict__ B1,
                       const float* __restrict__ gam, float sK) {
    int i = blockIdx.x * blockDim.x + threadIdx.x;
    const double PI = 3.14159265358979323846;
    if (i < 1024) {
        float2 v = make_float2(0.f, 0.f);
        if (i < 1000) {
            double alpha = PI * 1.33 / (5.61e-7 * 0.006);
            double x = (double)(i - 499) * 1e-6;
            double th = alpha * x * x;
            double s, c;
            sincos(th, &s, &c);
            v = make_float2((float)c, (float)s);
        }
        g_p[i] = v;
        {
            double ang = -2.0 * PI * (double)i / 1024.0;
            double s, c;
            sincos(ang, &s, &c);
            g_W1024[i] = make_float2((float)c, (float)s);
        }
        {
            float2 cv = make_float2(0.f, 0.f);
            long n = -1;
            if (i < 500) n = i;
            else if (i >= 525) n = 1024 - i;
            if (n >= 0) {
                double th = PI * (double)(n * n) / 500.0;
                double s, c;
                sincos(th, &s, &c);
                cv = make_float2((float)c, (float)s);
            }
            g_c[i] = cv;
        }
    }
    if (i < GN) {
        double th = PI * (double)((long)i * i) / 500.0;
        double s, c;
        sincos(th, &s, &c);
        g_chirp[i] = make_float2((float)c, (float)(-s));   // e^{-i th}
        double ang = -2.0 * PI * (double)i / (double)GN;
        double s2, c2;
        sincos(ang, &s2, &c2);
        g_W500i[i] = make_float2((float)c2, (float)(-s2));
    }
    if (i < 2 * 200 * 200) g_canvas[i] = 0.f;
    if (i < 128) g_intens[i] = 0.f;
    if (i < GN * GN) {
        float s, c;
        sincosf(mp[i], &s, &c);
        float m = mr[i];
        float2 b = B1[i];
        float er = m * c, ei = m * s;
        g_field[i] = make_float2(b.x * er - b.y * ei, b.x * ei + b.y * er);
        int u = i / GN, v2 = i % GN;
        int su = (u + 250) % GN, sv = (v2 + 250) % GN;
        g_tg[i] = sK * gam[su * GN + sv];
    }
}

// ---------------- direct 1024-DFT for the two kernel tables ----------------
__global__ __launch_bounds__(128) void k_tabdft() {
    __shared__ float rx[4], ry[4];
    int k = blockIdx.x;
    int which = blockIdx.y;
    const float2* src = which ? g_c : g_p;
    int t = threadIdx.x;
    int idx = (k * t) & 1023;
    int step = (k * 128) & 1023;
    float ax = 0.f, ay = 0.f;
    for (; t < 1024; t += 128) {
        float2 s = src[t];
        float2 w = g_W1024[idx];
        ax = fmaf(s.x, w.x, ax); ax = fmaf(-s.y, w.y, ax);
        ay = fmaf(s.x, w.y, ay); ay = fmaf(s.y, w.x, ay);
        idx = (idx + step) & 1023;
    }
    int lane = threadIdx.x & 31, wid = threadIdx.x >> 5;
#pragma unroll
    for (int o = 16; o > 0; o >>= 1) {
        ax += __shfl_down_sync(0xffffffffu, ax, o);
        ay += __shfl_down_sync(0xffffffffu, ay, o);
    }
    if (lane == 0) { rx[wid] = ax; ry[wid] = ay; }
    __syncthreads();
    if (threadIdx.x == 0) {
        float Sx = rx[0] + rx[1] + rx[2] + rx[3];
        float Sy = ry[0] + ry[1] + ry[2] + ry[3];
        float sc = which ? (1.0f / 1024.0f) : (1e-3f / 1024.0f);
        if (which) g_Kb[k] = make_float2(Sx * sc, Sy * sc);
        else       g_Kp[k] = make_float2(Sx * sc, Sy * sc);
    }
}

// ---------------- batched FFT-conv pass (radix-4 Stockham) -----------------
// 2 rows per block (grid 250), 256 threads. mode 0: propagation conv;
// mode 1: bluestein DFT. Output written transposed.
__global__ __launch_bounds__(256) void k_fconv(const float2* __restrict__ in,
                                               float2* __restrict__ out,
                                               int mode) {
    extern __shared__ float2 sm[];
    float2* buf0 = sm;          // [2][1024]
    float2* buf1 = sm + 2048;   // [2][1024]
    float2* sW   = sm + 4096;   // [1024]
    int r0 = blockIdx.x * 2;
    int tid = threadIdx.x;

    for (int i = tid; i < 1024; i += 256) sW[i] = g_W1024[i];

    for (int i = tid; i < 2048; i += 256) {
        int b = i >> 10, t = i & 1023;
        float2 v = make_float2(0.f, 0.f);
        if (t < 500) {
            v = in[(size_t)(r0 + b) * GN + t];
            if (mode) v = cmul(v, g_chirp[t]);
        }
        buf0[i] = v;
    }
    __syncthreads();

    float2 *cur = buf0, *nxt = buf1;
    int m = 1;
    // forward: 5 radix-4 stages
#pragma unroll 1
    for (int st = 0; st < 5; st++) {
#pragma unroll
        for (int ii = 0; ii < 2; ii++) {
            int i = tid + ii * 256;
            int b = i >> 8, j = i & 255;
            int base = b << 10;
            float2 x0 = cur[base + j];
            float2 x1 = cur[base + j + 256];
            float2 x2 = cur[base + j + 512];
            float2 x3 = cur[base + j + 768];
            int k = j & ~(m - 1);
            float2 t0 = cadd(x0, x2), t1 = csub(x0, x2);
            float2 t2 = cadd(x1, x3);
            float2 d  = csub(x1, x3);
            float2 t3 = make_float2(d.y, -d.x);      // -i * d
            int o = base + j + 3 * k;
            nxt[o]         = cadd(t0, t2);
            nxt[o + m]     = cmul(cadd(t1, t3), sW[k]);
            nxt[o + 2 * m] = cmul(csub(t0, t2), sW[2 * k]);
            nxt[o + 3 * m] = cmul(csub(t1, t3), sW[3 * k]);
        }
        float2* tsw = cur; cur = nxt; nxt = tsw;
        m <<= 2;
        __syncthreads();
    }

    // pointwise kernel multiply
    const float2* K = mode ? g_Kb : g_Kp;
    for (int i = tid; i < 2048; i += 256)
        cur[i] = cmul(cur[i], K[i & 1023]);
    __syncthreads();

    // inverse: 5 radix-4 stages, conjugated twiddles
    m = 1;
#pragma unroll 1
    for (int st = 0; st < 5; st++) {
#pragma unroll
        for (int ii = 0; ii < 2; ii++) {
            int i = tid + ii * 256;
            int b = i >> 8, j = i & 255;
            int base = b << 10;
            float2 x0 = cur[base + j];
            float2 x1 = cur[base + j + 256];
            float2 x2 = cur[base + j + 512];
            float2 x3 = cur[base + j + 768];
            int k = j & ~(m - 1);
            float2 t0 = cadd(x0, x2), t1 = csub(x0, x2);
            float2 t2 = cadd(x1, x3);
            float2 d  = csub(x1, x3);
            float2 t3 = make_float2(-d.y, d.x);      // +i * d
            int o = base + j + 3 * k;
            nxt[o]         = cadd(t0, t2);
            nxt[o + m]     = cmulc(cadd(t1, t3), sW[k]);
            nxt[o + 2 * m] = cmulc(csub(t0, t2), sW[2 * k]);
            nxt[o + 3 * m] = cmulc(csub(t1, t3), sW[3 * k]);
        }
        float2* tsw = cur; cur = nxt; nxt = tsw;
        m <<= 2;
        __syncthreads();
    }

    // extract + transposed write
    if (mode == 0) {
        for (int i = tid; i < 1000; i += 256) {
            int j = i >> 1, b = i & 1;
            out[(size_t)j * GN + r0 + b] = cur[(b << 10) + 500 + j];
        }
    } else {
        for (int i = tid; i < 1000; i += 256) {
            int k = i >> 1, b = i & 1;
            out[(size_t)k * GN + r0 + b] =
                cmul(cur[(b << 10) + k], g_chirp[k]);
        }
    }
}

// ---------------- per-emitter intensity: warp-owned emitter ranges ---------
__global__ __launch_bounds__(128) void k_emit(const int* __restrict__ xyz) {
    __shared__ float2 sfo[GN];
    __shared__ float  stg[GN];
    __shared__ float2 sW[GN];
    int u = blockIdx.x;

    const float2* fo = g_B + (size_t)u * GN;   // FO lives in g_B
    const float*  tg = g_tg + (size_t)u * GN;
    for (int i = threadIdx.x; i < GN; i += 128) {
        sfo[i] = fo[i];
        stg[i] = tg[i];
        sW[i]  = g_W500i[i];
    }
    __syncthreads();

    int lane = threadIdx.x & 31;
    int wid = threadIdx.x >> 5;

    for (int e = wid * 32; e < wid * 32 + 32; e++) {
        int x0 = xyz[e * 3 + 0];
        int z = xyz[e * 3 + 2];
        float xf = (float)(x0 - 100);
        int c = 249 + z;
        int idx = (c * lane) % GN;
        int step = (c * 32) % GN;

        float sx = 0.f, sy = 0.f;
        for (int v = lane; v < GN; v += 32) {
            float arg = stg[v] * xf;  // f32 rounding matches reference
            float nq = rintf(arg * 0.15915494309189535f);
            float rr = fmaf(nq, -6.28125f, arg);
            rr = fmaf(nq, -1.9353072e-3f, rr);
            float sn, cs;
            __sincosf(rr, &sn, &cs);
            float2 f = sfo[v];
            float pr = f.x * cs - f.y * sn;
            float pi = f.x * sn + f.y * cs;
            float2 w = sW[idx];
            sx = fmaf(pr, w.x, sx); sx = fmaf(-pi, w.y, sx);
            sy = fmaf(pr, w.y, sy); sy = fmaf(pi, w.x, sy);
            idx += step; if (idx >= GN) idx -= GN;
        }
#pragma unroll
        for (int o = 16; o > 0; o >>= 1) {
            sx += __shfl_down_sync(0xffffffffu, sx, o);
            sy += __shfl_down_sync(0xffffffffu, sy, o);
        }
        if (lane == 0)
            atomicAdd(&g_intens[e], (sx * sx + sy * sy) * 8e-9f);  // 1/500^3
    }
}

// ---------------- scatter psf patches into canvas --------------------------
__global__ void k_scatter(const int* __restrict__ xyz,
                          const float* __restrict__ psf) {
    int tid = blockIdx.x * blockDim.x + threadIdx.x;
    if (tid >= 128 * 961) return;
    int e = tid / 961, p = tid % 961;
    int b = e >> 6;
    int x0 = xyz[e * 3 + 0];
    int y0 = xyz[e * 3 + 1];
    int z = xyz[e * 3 + 2];
    int r = p / 31, cc = p % 31;
    float val = psf[z * 961 + p] * g_intens[e];
    int row = x0 + r - 15;
    int col = y0 + cc - 15;
    atomicAdd(&g_canvas[b * 40000 + row * 200 + col], val);
}

// ---------------- noise model + output -------------------------------------
__global__ void k_final(const float* __restrict__ ng,
                        const float* __restrict__ np_,
                        float* __restrict__ out) {
    int i = blockIdx.x * blockDim.x + threadIdx.x;
    if (i >= 2 * 200 * 200) return;
    float a = g_canvas[i] / 50000.0f + 100.0f;  // imgs3D + UNIF_BG
    float b = a + 100000.0f;
    float t = fmaf(2.0e8f, ng[i], 3.0e8f);
    float inp = b + t;
    if (inp <= 0.0f) inp = 0.0f;
    float noisy = inp + 100.0f * sqrtf(inp) * np_[i];
    if (noisy <= 10.0f) noisy = 1.0f;
    noisy = fminf(noisy, 4.0e9f);
    out[i] = noisy / 4.0e9f;
}

// ---------------------------------------------------------------------------
extern "C" void kernel_launch(void* const* d_in, const int* in_sizes, int n_in,
                              void* d_out, int out_size) {
    const float*  mask_param = (const float*)d_in[0];
    const int*    xyz        = (const int*)d_in[1];
    // d_in[2] = nphotons (unused by reference)
    const float2* B1         = (const float2*)d_in[3];
    // d_in[4] = Q1 (replaced by separable p-vector)
    const float*  mask_real  = (const float*)d_in[5];
    const float*  gamma_c    = (const float*)d_in[6];
    const float*  psf        = (const float*)d_in[7];
    const float*  ngauss     = (const float*)d_in[8];
    const float*  npoiss     = (const float*)d_in[9];
    float*        out        = (float*)d_out;

    double Kd = 2.0 * 1.33 * 3.14159265358979323846 / 5.61e-7;
    float sK = (float)(Kd * 1e-6);

    float2 *fld, *bA, *bB;
    cudaGetSymbolAddress((void**)&fld, g_field);
    cudaGetSymbolAddress((void**)&bA, g_A);
    cudaGetSymbolAddress((void**)&bB, g_B);

    const int BT = 256;
    const int SMEM_FFT = 5120 * (int)sizeof(float2);  // 40KB

    // fused setup
    k_prep<<<(GN * GN + BT - 1) / BT, BT>>>(mask_param, mask_real, B1,
                                            gamma_c, sK);

    // kernel-spectrum tables Kp, Kb
    k_tabdft<<<dim3(1024, 2), 128>>>();

    // out = 1e-6 T f T^T (two conv passes), FO = F out F^T (two bluestein)
    k_fconv<<<250, 256, SMEM_FFT>>>(fld, bA, 0);
    k_fconv<<<250, 256, SMEM_FFT>>>(bA, bB, 0);
    k_fconv<<<250, 256, SMEM_FFT>>>(bB, bA, 1);
    k_fconv<<<250, 256, SMEM_FFT>>>(bA, bB, 1);   // FO -> g_B

    // per-emitter intensities (4 warps x 32 emitters per block)
    k_emit<<<GN, 128>>>(xyz);

    // patches -> canvas
    k_scatter<<<(128 * 961 + BT - 1) / BT, BT>>>(xyz, psf);

    // noise model -> output
    k_final<<<(2 * 200 * 200 + BT - 1) / BT, BT>>>(ngauss, npoiss, out);
}